// round 7
// baseline (speedup 1.0000x reference)
#include <cuda_runtime.h>
#include <cstdint>

// Problem constants (fixed by the dataset)
#define BB 32
#define TT 2048
#define KK 512
#define MM 1024          // MAX_MASKED
#define MU 1024          // MAX_UNMASKED
#define K4 (KK / 4)      // 128 float4 per row
#define LN_EPS 1e-5f

// Warp-per-row design: block = 4 warps, each warp fully owns one output row
// (32 lanes x 4 float4 chunks = 128 float4 = 512 floats). LayerNorm reduction
// is warp-local shuffles only -> NO __syncthreads, NO shared memory, warps
// fully decoupled for latency hiding. Low register footprint -> 12 blocks/SM.
// Outputs (concatenated in d_out):
//   out0: unmasked_embeddings (B, MU, K)
//   out1: mask_embedding      (B, MM, K)
//   out2: unmasked_positions  (B, MU, K)
__global__ __launch_bounds__(128, 12)
void mae_masking_kernel(
    const float* __restrict__ tok,    // (B, T, K)
    const float* __restrict__ pe,     // (T, K)
    const float* __restrict__ mw,     // (K, 1)
    const float* __restrict__ gamma,  // (K,)
    const float* __restrict__ beta,   // (K,)
    const int*   __restrict__ midx,   // (B, MM)
    const int*   __restrict__ uidx,   // (B, MU)
    const int*   __restrict__ nm,     // (B,)
    const int*   __restrict__ nu,     // (B,)
    float* __restrict__ out)
{
    const int wid  = threadIdx.x >> 5;          // warp in block: 0..3
    const int lane = threadIdx.x & 31;
    const int j    = blockIdx.x * 4 + wid;      // row this warp owns
    const int b    = blockIdx.y;

    const float4* __restrict__ pe4  = reinterpret_cast<const float4*>(pe);
    const float4* __restrict__ tok4 = reinterpret_cast<const float4*>(tok);
    const float4* __restrict__ mw4  = reinterpret_cast<const float4*>(mw);
    const float4* __restrict__ g4   = reinterpret_cast<const float4*>(gamma);
    const float4* __restrict__ be4  = reinterpret_cast<const float4*>(beta);
    float4* __restrict__ o0 = reinterpret_cast<float4*>(out);
    float4* __restrict__ o1 = o0 + (size_t)BB * MU * K4;
    float4* __restrict__ o2 = o1 + (size_t)BB * MM * K4;

    const float4 zero = make_float4(0.f, 0.f, 0.f, 0.f);
    const size_t rowo = ((size_t)b * MU + (size_t)j) * K4 + (size_t)lane;

    // ---------------- copy path: tok gather + pe gather ----------------
    {
        const bool vu = j < nu[b];
        const int  u  = uidx[b * MU + j];                 // j < MU always: safe
        const size_t pr = (size_t)u * K4 + lane;
        const size_t tr = ((size_t)b * TT + (size_t)u) * K4 + lane;

        if (vu) {
            #pragma unroll
            for (int p = 0; p < 2; p++) {                 // 2 chunks x 4 loads
                const int c0 = p * 64, c1 = p * 64 + 32;
                float4 pa = pe4[pr + c0];
                float4 pb = pe4[pr + c1];
                float4 ta = tok4[tr + c0];
                float4 tb = tok4[tr + c1];
                __stcs(&o2[rowo + c0], pa);
                __stcs(&o2[rowo + c1], pb);
                __stcs(&o0[rowo + c0], ta);
                __stcs(&o0[rowo + c1], tb);
            }
        } else {
            #pragma unroll
            for (int i = 0; i < 4; i++) {
                __stcs(&o0[rowo + i * 32], zero);
                __stcs(&o2[rowo + i * 32], zero);
            }
        }
    }

    // ---------------- mask LayerNorm path (warp-local reduce) ----------------
    {
        const bool vm = j < nm[b];                        // warp-uniform
        if (vm) {
            const int m = midx[b * MM + j];
            const size_t mr = (size_t)m * K4 + lane;

            float s = 0.f, ss = 0.f;
            #pragma unroll
            for (int i = 0; i < 4; i++) {
                const float4 pm = pe4[mr + i * 32];
                const float4 w  = mw4[lane + i * 32];
                const float x0 = pm.x + w.x, x1 = pm.y + w.y;
                const float x2 = pm.z + w.z, x3 = pm.w + w.w;
                s  += x0 + x1 + x2 + x3;
                ss += x0 * x0 + x1 * x1 + x2 * x2 + x3 * x3;
            }
            #pragma unroll
            for (int o = 16; o > 0; o >>= 1) {
                s  += __shfl_xor_sync(0xffffffffu, s,  o);
                ss += __shfl_xor_sync(0xffffffffu, ss, o);
            }
            const float mean = s * (1.0f / KK);
            const float var  = ss * (1.0f / KK) - mean * mean;
            const float inv  = rsqrtf(var + LN_EPS);

            #pragma unroll
            for (int i = 0; i < 4; i++) {
                const float4 pm = pe4[mr + i * 32];       // L1 hit (just read)
                const float4 w  = mw4[lane + i * 32];     // L1 hit
                const float4 g  = g4[lane + i * 32];
                const float4 be = be4[lane + i * 32];
                float4 ln;
                ln.x = (pm.x + w.x - mean) * inv * g.x + be.x;
                ln.y = (pm.y + w.y - mean) * inv * g.y + be.y;
                ln.z = (pm.z + w.z - mean) * inv * g.z + be.z;
                ln.w = (pm.w + w.w - mean) * inv * g.w + be.w;
                __stcs(&o1[rowo + i * 32], ln);
            }
        } else {
            #pragma unroll
            for (int i = 0; i < 4; i++)
                __stcs(&o1[rowo + i * 32], zero);
        }
    }
}

extern "C" void kernel_launch(void* const* d_in, const int* in_sizes, int n_in,
                              void* d_out, int out_size)
{
    const float* tok   = (const float*)d_in[0];
    const float* pe    = (const float*)d_in[1];
    const float* mw    = (const float*)d_in[2];
    const float* gamma = (const float*)d_in[3];
    const float* beta  = (const float*)d_in[4];
    const int*   midx  = (const int*)d_in[5];
    const int*   uidx  = (const int*)d_in[6];
    const int*   nm    = (const int*)d_in[7];
    const int*   nu    = (const int*)d_in[8];

    dim3 grid(MU / 4, BB);   // 256 x 32 blocks, 4 warps each = 1 row/warp
    dim3 block(128);
    mae_masking_kernel<<<grid, block>>>(tok, pe, mw, gamma, beta,
                                        midx, uidx, nm, nu, (float*)d_out);
}